// round 1
// baseline (speedup 1.0000x reference)
#include <cuda_runtime.h>

#define N_MAX   100000
#define FIN     512
#define HID     16
#define NC      7
#define H2      8   // padded layer-2 width

// -------- scratch (static device globals; no allocation allowed) --------
__device__ float g_deg [N_MAX];
__device__ float g_dinv[N_MAX];
__device__ float g_xw  [N_MAX * HID];   // x @ W1
__device__ float g_agg1[N_MAX * HID];   // layer-1 neighbor sums
__device__ float g_h1w [N_MAX * H2];    // relu(h1) @ W2, padded to 8
__device__ float g_agg2[N_MAX * H2];    // layer-2 neighbor sums

__device__ __forceinline__ void red_add_v4(float* p, float4 v) {
    asm volatile("red.global.add.v4.f32 [%0], {%1,%2,%3,%4};"
                 :: "l"(p), "f"(v.x), "f"(v.y), "f"(v.z), "f"(v.w)
                 : "memory");
}

// -------- init: zero accumulators, deg = 1 (self loop) --------
__global__ void k_init(int n) {
    int stride = gridDim.x * blockDim.x;
    int t0 = blockIdx.x * blockDim.x + threadIdx.x;
    for (int t = t0; t < n * HID; t += stride) g_agg1[t] = 0.f;
    for (int t = t0; t < n * H2;  t += stride) g_agg2[t] = 0.f;
    for (int t = t0; t < n;       t += stride) g_deg[t]  = 1.f;
}

// -------- in-degree count over col --------
__global__ void k_deg(const int* __restrict__ col, int ne) {
    int e = blockIdx.x * blockDim.x + threadIdx.x;
    if (e < ne) atomicAdd(&g_deg[col[e]], 1.0f);
}

// -------- dinv = rsqrt(deg) --------
__global__ void k_dinv(int n) {
    int i = blockIdx.x * blockDim.x + threadIdx.x;
    if (i < n) g_dinv[i] = rsqrtf(g_deg[i]);
}

// -------- xw = x @ W1  (one node per thread, W1 in smem) --------
__global__ void k_gemm1(const float* __restrict__ x,
                        const float* __restrict__ W1, int n) {
    __shared__ float sW[FIN * HID];  // 32 KB
    for (int i = threadIdx.x; i < FIN * HID; i += blockDim.x) sW[i] = W1[i];
    __syncthreads();

    int nd = blockIdx.x * blockDim.x + threadIdx.x;
    if (nd >= n) return;

    float acc[HID];
#pragma unroll
    for (int j = 0; j < HID; j++) acc[j] = 0.f;

    const float4* xr = (const float4*)(x + (size_t)nd * FIN);
#pragma unroll 4
    for (int k4 = 0; k4 < FIN / 4; k4++) {
        float4 xv = __ldg(&xr[k4]);
        float xs[4] = {xv.x, xv.y, xv.z, xv.w};
#pragma unroll
        for (int u = 0; u < 4; u++) {
            const float4* wr = (const float4*)(&sW[(k4 * 4 + u) * HID]);
            float xk = xs[u];
#pragma unroll
            for (int j4 = 0; j4 < 4; j4++) {
                float4 w = wr[j4];
                acc[j4 * 4 + 0] += xk * w.x;
                acc[j4 * 4 + 1] += xk * w.y;
                acc[j4 * 4 + 2] += xk * w.z;
                acc[j4 * 4 + 3] += xk * w.w;
            }
        }
    }
    float4* o = (float4*)(&g_xw[(size_t)nd * HID]);
#pragma unroll
    for (int j4 = 0; j4 < 4; j4++)
        o[j4] = make_float4(acc[j4 * 4], acc[j4 * 4 + 1],
                            acc[j4 * 4 + 2], acc[j4 * 4 + 3]);
}

// -------- layer-1 edge aggregation: 4 lanes per edge (16 floats) --------
__global__ void k_agg1(const int* __restrict__ row,
                       const int* __restrict__ col, int ne) {
    int t = blockIdx.x * blockDim.x + threadIdx.x;
    int e = t >> 2, q = t & 3;
    if (e >= ne) return;
    int r = __ldg(&row[e]);
    int c = __ldg(&col[e]);
    float w = __ldg(&g_dinv[r]) * __ldg(&g_dinv[c]);
    float4 v = *(const float4*)(&g_xw[(size_t)r * HID + q * 4]);
    v.x *= w; v.y *= w; v.z *= w; v.w *= w;
    red_add_v4(&g_agg1[(size_t)c * HID + q * 4], v);
}

// -------- h1 = relu(agg1 + dinv^2*xw + b1); h1w = h1 @ W2 --------
__global__ void k_h1(const float* __restrict__ b1,
                     const float* __restrict__ W2, int n) {
    __shared__ float sW2[HID * NC];
    __shared__ float sb1[HID];
    if (threadIdx.x < HID * NC) sW2[threadIdx.x] = W2[threadIdx.x];
    if (threadIdx.x < HID)      sb1[threadIdx.x] = b1[threadIdx.x];
    __syncthreads();

    int i = blockIdx.x * blockDim.x + threadIdx.x;
    if (i >= n) return;

    float d2 = g_dinv[i] * g_dinv[i];
    float h[HID];
#pragma unroll
    for (int j = 0; j < HID; j++) {
        float v = g_agg1[(size_t)i * HID + j] + d2 * g_xw[(size_t)i * HID + j] + sb1[j];
        h[j] = v > 0.f ? v : 0.f;
    }
    float y[H2];
#pragma unroll
    for (int j = 0; j < H2; j++) y[j] = 0.f;
#pragma unroll
    for (int k = 0; k < HID; k++) {
        float hk = h[k];
#pragma unroll
        for (int j = 0; j < NC; j++) y[j] += hk * sW2[k * NC + j];
    }
    float4* o = (float4*)(&g_h1w[(size_t)i * H2]);
    o[0] = make_float4(y[0], y[1], y[2], y[3]);
    o[1] = make_float4(y[4], y[5], y[6], 0.f);
}

// -------- layer-2 edge aggregation: 2 lanes per edge (8 floats) --------
__global__ void k_agg2(const int* __restrict__ row,
                       const int* __restrict__ col, int ne) {
    int t = blockIdx.x * blockDim.x + threadIdx.x;
    int e = t >> 1, q = t & 1;
    if (e >= ne) return;
    int r = __ldg(&row[e]);
    int c = __ldg(&col[e]);
    float w = __ldg(&g_dinv[r]) * __ldg(&g_dinv[c]);
    float4 v = *(const float4*)(&g_h1w[(size_t)r * H2 + q * 4]);
    v.x *= w; v.y *= w; v.z *= w; v.w *= w;
    red_add_v4(&g_agg2[(size_t)c * H2 + q * 4], v);
}

// -------- out = agg2 + dinv^2*h1w + b2 --------
__global__ void k_out(float* __restrict__ out, const float* __restrict__ b2, int n) {
    int i = blockIdx.x * blockDim.x + threadIdx.x;
    if (i >= n) return;
    float d2 = g_dinv[i] * g_dinv[i];
#pragma unroll
    for (int j = 0; j < NC; j++)
        out[(size_t)i * NC + j] =
            g_agg2[(size_t)i * H2 + j] + d2 * g_h1w[(size_t)i * H2 + j] + __ldg(&b2[j]);
}

extern "C" void kernel_launch(void* const* d_in, const int* in_sizes, int n_in,
                              void* d_out, int out_size) {
    const float* x  = (const float*)d_in[0];
    const int*   ei = (const int*)  d_in[1];
    const float* W1 = (const float*)d_in[2];
    const float* b1 = (const float*)d_in[3];
    const float* W2 = (const float*)d_in[4];
    const float* b2 = (const float*)d_in[5];

    int n  = in_sizes[0] / FIN;   // 100000
    int ne = in_sizes[1] / 2;     // 3200000
    const int* row = ei;          // source
    const int* col = ei + ne;     // target

    k_init<<<148 * 8, 256>>>(n);
    k_deg <<<(ne + 255) / 256, 256>>>(col, ne);
    k_dinv<<<(n + 255) / 256, 256>>>(n);
    k_gemm1<<<(n + 255) / 256, 256>>>(x, W1, n);
    k_agg1<<<((ne * 4) + 255) / 256, 256>>>(row, col, ne);
    k_h1  <<<(n + 255) / 256, 256>>>(b1, W2, n);
    k_agg2<<<((ne * 2) + 255) / 256, 256>>>(row, col, ne);
    k_out <<<(n + 255) / 256, 256>>>((float*)d_out, b2, n);
}